// round 4
// baseline (speedup 1.0000x reference)
#include <cuda_runtime.h>

#define NAG    12
#define NENV   4096
#define NNODE  (NENV*NAG)
#define TPB    384

// shared float offsets
#define OFF_WA   0        // 8192 (We1[0:128] / Wh1)
#define OFF_WB   8192     // 4096 (Wemb / We2 / Wh2)
#define OFF_ENV  12288    // two env blocks
// per-env offsets (relative)
#define EO_H     0        // 12x64
#define EO_P2    768      // P2 float2[12][32] ; reused as t1 [12][64]
#define EO_AGG   1536     // 12x64
#define EO_XS0   2304     // 144
#define EO_XS1   2448     // 144
#define EO_RAD   2592     // 132x4
#define EO_H0S   3120     // 12x32
#define ENVSZ    3504
#define OFF_MS   (OFF_ENV + 2*ENVSZ)   // 12 warps x 512
#define SMEM_FLOATS (OFF_MS + 12*512)
#define SMEM_BYTES  (SMEM_FLOATS*4)

__device__ __forceinline__ float siluf(float v) { return v / (1.0f + __expf(-v)); }

extern "C" __global__ void __launch_bounds__(TPB, 2)
egnn_kernel(const float* __restrict__ h0,   const float* __restrict__ x0,
            const float* __restrict__ Wemb, const float* __restrict__ bemb,
            const float* __restrict__ We1,  const float* __restrict__ be1,
            const float* __restrict__ We2,  const float* __restrict__ be2,
            const float* __restrict__ Wx,   const float* __restrict__ bx,
            const float* __restrict__ Wh1,  const float* __restrict__ bh1,
            const float* __restrict__ Wh2,  const float* __restrict__ bh2,
            const float* __restrict__ w_act,const float* __restrict__ log_std,
            float* __restrict__ out)
{
    extern __shared__ float sm[];
    float* WA  = sm + OFF_WA;
    float* WB  = sm + OFF_WB;

    const int tid  = threadIdx.x;
    const int w    = tid >> 5;
    const int lane = tid & 31;
    const int slot = w >= 6;          // which env half this warp serves
    const int wl   = w - slot * 6;    // warp-in-env 0..5
    const int env0 = blockIdx.x * 2;
    const int base = (env0 + slot) * NAG;

    float* es  = sm + OFF_ENV + slot * ENVSZ;
    float* hs  = es + EO_H;
    float* P2p = es + EO_P2;
    float* t1s = es + EO_P2;          // phase-disjoint reuse
    float* agg = es + EO_AGG;
    float* xs0 = es + EO_XS0;
    float* xs1 = es + EO_XS1;
    float* rad = es + EO_RAD;
    float* h0s = es + EO_H0S;
    float* ms  = sm + OFF_MS;

    const int iA = 2 * wl, iB = 2 * wl + 1;

    // ---------- phase 0: stage x, h0, W_embed ; embed ----------
    for (int t = tid; t < 2 * NAG * NAG; t += TPB) {
        int s2 = t / 144, idx = t - s2 * 144;
        sm[OFF_ENV + s2 * ENVSZ + EO_XS0 + idx] = __ldg(&x0[(env0 + s2) * 144 + idx]);
    }
    for (int t = tid; t < 2 * NAG * 32; t += TPB) {
        int s2 = t / 384, idx = t - s2 * 384;
        sm[OFF_ENV + s2 * ENVSZ + EO_H0S + idx] = __ldg(&h0[(env0 + s2) * 384 + idx]);
    }
    {
        float4* q = (float4*)WB;
        const float4* g = (const float4*)Wemb;
        for (int i = tid; i < 512; i += TPB) q[i] = __ldg(&g[i]);
    }
    __syncthreads();
    {   // h = h0 @ Wemb + bemb (2 nodes per warp)
        float a0A = __ldg(&bemb[lane]),      a1A = __ldg(&bemb[lane + 32]);
        float a0B = a0A, a1B = a1A;
        #pragma unroll
        for (int k = 0; k < 32; k++) {
            float w0 = WB[k*64 + lane], w1 = WB[k*64 + lane + 32];
            float hA = h0s[iA*32 + k],  hB = h0s[iB*32 + k];
            a0A += hA*w0; a1A += hA*w1;
            a0B += hB*w0; a1B += hB*w1;
        }
        hs[iA*64 + lane] = a0A; hs[iA*64 + lane + 32] = a1A;
        hs[iB*64 + lane] = a0B; hs[iB*64 + lane + 32] = a1B;
    }

    // ---------- layers ----------
    for (int l = 0; l < 2; l++) {
        __syncthreads();
        float* xsr = (l == 0) ? xs0 : xs1;
        float* xsw = (l == 0) ? xs1 : xs0;
        {   // stage We1 rows 0..127 -> WA, We2 -> WB
            float4* q = (float4*)WA;
            const float4* g = (const float4*)(We1 + l * 8448);
            for (int i = tid; i < 2048; i += TPB) q[i] = __ldg(&g[i]);
            float4* q2 = (float4*)WB;
            const float4* g2 = (const float4*)(We2 + l * 4096);
            for (int i = tid; i < 1024; i += TPB) q2[i] = __ldg(&g2[i]);
        }
        if (tid < 264) {   // radial per edge, both envs
            int s2 = tid / 132, e = tid - s2 * 132;
            float* xp = sm + OFF_ENV + s2 * ENVSZ + EO_XS0 + (l ? (EO_XS1 - EO_XS0) : 0);
            float* rp = sm + OFF_ENV + s2 * ENVSZ + EO_RAD;
            int i = e / 11, tt = e - 11 * i, j = tt + (tt >= i);
            float s0 = 0.f, s1 = 0.f, s2v = 0.f, s3 = 0.f;
            #pragma unroll
            for (int d = 0; d < 3; d++) {
                float d0 = xp[i*12 + d*4 + 0] - xp[j*12 + d*4 + 0]; s0  += d0*d0;
                float d1 = xp[i*12 + d*4 + 1] - xp[j*12 + d*4 + 1]; s1  += d1*d1;
                float d2 = xp[i*12 + d*4 + 2] - xp[j*12 + d*4 + 2]; s2v += d2*d2;
                float d3 = xp[i*12 + d*4 + 3] - xp[j*12 + d*4 + 3]; s3  += d3*d3;
            }
            ((float4*)rp)[e] = make_float4(s0, s1, s2v, s3);
        }
        __syncthreads();

        // ---- P-phase (2 nodes per warp): P1 in regs, P2 -> smem ----
        float PiA0, PiA1, PiB0, PiB1;
        {
            float b0 = __ldg(&be1[l*64 + lane]), b1 = __ldg(&be1[l*64 + lane + 32]);
            float a0A = b0, a1A = b1, a2A = 0.f, a3A = 0.f;
            float a0B = b0, a1B = b1, a2B = 0.f, a3B = 0.f;
            #pragma unroll
            for (int k = 0; k < 64; k++) {
                float w0 = WA[k*64 + lane],        w1 = WA[k*64 + lane + 32];
                float w2 = WA[(64+k)*64 + lane],   w3 = WA[(64+k)*64 + lane + 32];
                float hA = hs[iA*64 + k], hB = hs[iB*64 + k];
                a0A += hA*w0; a1A += hA*w1; a2A += hA*w2; a3A += hA*w3;
                a0B += hB*w0; a1B += hB*w1; a2B += hB*w2; a3B += hB*w3;
            }
            PiA0 = a0A; PiA1 = a1A; PiB0 = a0B; PiB1 = a1B;
            ((float2*)P2p)[iA*32 + lane] = make_float2(a2A, a3A);
            ((float2*)P2p)[iB*32 + lane] = make_float2(a2B, a3B);
        }
        __syncthreads();

        // ---- edge phase: warp owns nodes iA, iB (22 edges) ----
        {
            const float4 wxA = __ldg((const float4*)&Wx[l*256 + lane*4]);
            const float4 wxB = __ldg((const float4*)&Wx[l*256 + (lane+32)*4]);
            const float4 bxv = __ldg((const float4*)&bx[l*4]);
            const float be2a = __ldg(&be2[l*64 + lane]);
            const float be2b = __ldg(&be2[l*64 + lane + 32]);
            float wrA[4], wrB[4];
            #pragma unroll
            for (int v = 0; v < 4; v++) {
                wrA[v] = __ldg(&We1[l*8448 + (128+v)*64 + lane]);
                wrB[v] = __ldg(&We1[l*8448 + (128+v)*64 + lane + 32]);
            }
            const float xiA = (lane < 12) ? xsr[iA*12 + lane] : 0.f;
            const float xiB = (lane < 12) ? xsr[iB*12 + lane] : 0.f;
            float agA0 = 0.f, agB0 = 0.f, agA1 = 0.f, agB1 = 0.f;
            float dx0 = 0.f, dx1 = 0.f;
            float* msw = ms + w * 512;

            #pragma unroll
            for (int g0 = 0; g0 < 22; g0 += 8) {
                const int cnt = (22 - g0 < 8) ? (22 - g0) : 8;
                // MLP1
                #pragma unroll
                for (int gg = 0; gg < 8; gg++) if (gg < cnt) {
                    const int t = g0 + gg;
                    const int i  = (t < 11) ? iA : iB;
                    const int tt = (t < 11) ? t : (t - 11);
                    const int j  = tt + (tt >= i);
                    float2 pj = ((const float2*)P2p)[j*32 + lane];
                    float4 rv = ((const float4*)rad)[i*11 + tt];
                    float P1a = (t < 11) ? PiA0 : PiB0;
                    float P1b = (t < 11) ? PiA1 : PiB1;
                    float aA = P1a + pj.x
                             + rv.x*wrA[0] + rv.y*wrA[1] + rv.z*wrA[2] + rv.w*wrA[3];
                    float aB = P1b + pj.y
                             + rv.x*wrB[0] + rv.y*wrB[1] + rv.z*wrB[2] + rv.w*wrB[3];
                    msw[gg*64 + lane]      = siluf(aA);
                    msw[gg*64 + lane + 32] = siluf(aB);
                }
                __syncwarp();
                // MLP2: weights read once per k4 for up to 8 edges
                float acc0[8], acc1[8];
                #pragma unroll
                for (int gg = 0; gg < 8; gg++) { acc0[gg] = be2a; acc1[gg] = be2b; }
                #pragma unroll
                for (int k4 = 0; k4 < 16; k4++) {
                    float w00 = WB[(4*k4+0)*64 + lane];
                    float w01 = WB[(4*k4+1)*64 + lane];
                    float w02 = WB[(4*k4+2)*64 + lane];
                    float w03 = WB[(4*k4+3)*64 + lane];
                    float w10 = WB[(4*k4+0)*64 + lane + 32];
                    float w11 = WB[(4*k4+1)*64 + lane + 32];
                    float w12 = WB[(4*k4+2)*64 + lane + 32];
                    float w13 = WB[(4*k4+3)*64 + lane + 32];
                    #pragma unroll
                    for (int gg = 0; gg < 8; gg++) if (gg < cnt) {
                        float4 aq = *(const float4*)&msw[gg*64 + k4*4];
                        acc0[gg] += aq.x*w00 + aq.y*w01 + aq.z*w02 + aq.w*w03;
                        acc1[gg] += aq.x*w10 + aq.y*w11 + aq.z*w12 + aq.w*w13;
                    }
                }
                // epilogue
                #pragma unroll
                for (int gg = 0; gg < 8; gg++) if (gg < cnt) {
                    const int t = g0 + gg;
                    const int tt = (t < 11) ? t : (t - 11);
                    const int i  = (t < 11) ? iA : iB;
                    const int j  = tt + (tt >= i);
                    float m0  = siluf(acc0[gg]);
                    float m1v = siluf(acc1[gg]);
                    if (t < 11) { agA0 += m0; agB0 += m1v; }
                    else        { agA1 += m0; agB1 += m1v; }
                    float p0 = m0*wxA.x + m1v*wxB.x;
                    float p1 = m0*wxA.y + m1v*wxB.y;
                    float p2 = m0*wxA.z + m1v*wxB.z;
                    float p3 = m0*wxA.w + m1v*wxB.w;
                    #pragma unroll
                    for (int off = 16; off; off >>= 1) {
                        p0 += __shfl_xor_sync(0xffffffffu, p0, off);
                        p1 += __shfl_xor_sync(0xffffffffu, p1, off);
                        p2 += __shfl_xor_sync(0xffffffffu, p2, off);
                        p3 += __shfl_xor_sync(0xffffffffu, p3, off);
                    }
                    if (lane < 12) {
                        int v = lane & 3;
                        float wc = (v == 0) ? (p0 + bxv.x) :
                                   (v == 1) ? (p1 + bxv.y) :
                                   (v == 2) ? (p2 + bxv.z) : (p3 + bxv.w);
                        float xi = (t < 11) ? xiA : xiB;
                        float d  = (xi - xsr[j*12 + lane]) * wc;
                        if (t < 11) dx0 += d; else dx1 += d;
                    }
                }
                __syncwarp();
            }
            agg[iA*64 + lane]      = agA0;
            agg[iA*64 + lane + 32] = agB0;
            agg[iB*64 + lane]      = agA1;
            agg[iB*64 + lane + 32] = agB1;
            if (lane < 12) {
                xsw[iA*12 + lane] = xiA + dx0 * (1.0f / 11.0f);
                xsw[iB*12 + lane] = xiB + dx1 * (1.0f / 11.0f);
            }
        }
        __syncthreads();
        {   // stage Wh1 -> WA, Wh2 -> WB
            float4* q = (float4*)WA;
            const float4* g = (const float4*)(Wh1 + l * 8192);
            for (int i = tid; i < 2048; i += TPB) q[i] = __ldg(&g[i]);
            float4* q2 = (float4*)WB;
            const float4* g2 = (const float4*)(Wh2 + l * 4096);
            for (int i = tid; i < 1024; i += TPB) q2[i] = __ldg(&g2[i]);
        }
        __syncthreads();

        // t1 = silu([h, agg] @ Wh1 + bh1)
        {
            float b0 = __ldg(&bh1[l*64 + lane]), b1 = __ldg(&bh1[l*64 + lane + 32]);
            float a0A = b0, a1A = b1, a0B = b0, a1B = b1;
            #pragma unroll
            for (int k = 0; k < 64; k++) {
                float w0 = WA[k*64 + lane], w1 = WA[k*64 + lane + 32];
                float hA = hs[iA*64 + k],   hB = hs[iB*64 + k];
                a0A += hA*w0; a1A += hA*w1;
                a0B += hB*w0; a1B += hB*w1;
            }
            #pragma unroll
            for (int k = 0; k < 64; k++) {
                float w0 = WA[(64+k)*64 + lane], w1 = WA[(64+k)*64 + lane + 32];
                float gA = agg[iA*64 + k],       gB = agg[iB*64 + k];
                a0A += gA*w0; a1A += gA*w1;
                a0B += gB*w0; a1B += gB*w1;
            }
            float s0A = siluf(a0A), s1A = siluf(a1A);
            float s0B = siluf(a0B), s1B = siluf(a1B);
            __syncthreads();   // P2p (aliased by t1s) fully consumed before overwrite
            t1s[iA*64 + lane] = s0A; t1s[iA*64 + lane + 32] = s1A;
            t1s[iB*64 + lane] = s0B; t1s[iB*64 + lane + 32] = s1B;
        }
        __syncthreads();
        // h += t1 @ Wh2 + bh2
        {
            float b0 = __ldg(&bh2[l*64 + lane]), b1 = __ldg(&bh2[l*64 + lane + 32]);
            float a0A = b0, a1A = b1, a0B = b0, a1B = b1;
            #pragma unroll
            for (int k = 0; k < 64; k++) {
                float w0 = WB[k*64 + lane], w1 = WB[k*64 + lane + 32];
                float tA = t1s[iA*64 + k],  tB = t1s[iB*64 + k];
                a0A += tA*w0; a1A += tA*w1;
                a0B += tB*w0; a1B += tB*w1;
            }
            hs[iA*64 + lane]      += a0A;
            hs[iA*64 + lane + 32] += a1A;
            hs[iB*64 + lane]      += a0B;
            hs[iB*64 + lane + 32] += a1B;
        }
    }
    __syncthreads();
    // ---------- output: mu = x . w_act (final x in xs0 of each env) ----------
    if (tid < 2 * NAG * 3) {
        int s2 = tid / 36, r = tid - s2 * 36;
        int a = r / 3, d = r - 3 * a;
        const float* xp = sm + OFF_ENV + s2 * ENVSZ + EO_XS0;
        float mu = 0.f;
        #pragma unroll
        for (int v = 0; v < 4; v++) mu += xp[a*12 + d*4 + v] * __ldg(&w_act[v]);
        int b2 = (env0 + s2) * NAG;
        out[(b2 + a) * 3 + d] = mu;
        out[NNODE * 3 + (b2 + a) * 3 + d] =
            -__ldg(&log_std[d]) - 0.91893853320467274178f;
    }
}

extern "C" void kernel_launch(void* const* d_in, const int* in_sizes, int n_in,
                              void* d_out, int out_size)
{
    (void)in_sizes; (void)n_in; (void)out_size;
    cudaFuncSetAttribute(egnn_kernel,
                         cudaFuncAttributeMaxDynamicSharedMemorySize, SMEM_BYTES);
    egnn_kernel<<<NENV/2, TPB, SMEM_BYTES>>>(
        (const float*)d_in[0],  (const float*)d_in[1],
        (const float*)d_in[2],  (const float*)d_in[3],
        (const float*)d_in[4],  (const float*)d_in[5],
        (const float*)d_in[6],  (const float*)d_in[7],
        (const float*)d_in[8],  (const float*)d_in[9],
        (const float*)d_in[10], (const float*)d_in[11],
        (const float*)d_in[12], (const float*)d_in[13],
        (const float*)d_in[14], (const float*)d_in[15],
        (float*)d_out);
}

// round 6
// speedup vs baseline: 1.3873x; 1.3873x over previous
#include <cuda_runtime.h>

#define NAG    12
#define NENV   4096
#define NNODE  (NENV*NAG)
#define TPB    192

// shared float offsets
#define OFF_WA   0        // 4096 (64x64 chunk of We1 / Wh1)
#define OFF_WB   4096     // 4096 (Wemb / We2 / Wh2)
#define OFF_H    8192     // 12x64
#define OFF_P2   8960     // P2 float2[12][32] ; reused as t1 [12][64]
#define OFF_AGG  9728     // 12x64
#define OFF_XS0  10496    // 144
#define OFF_XS1  10640    // 144
#define OFF_RAD  10784    // 132x4
#define OFF_MS   11312    // 6 warps x 256 = 1536 ; h0s (384) aliased here
#define OFF_H0S  OFF_MS
#define SMEM_FLOATS 12848
#define SMEM_BYTES  (SMEM_FLOATS*4)

__device__ __forceinline__ float siluf(float v) { return v / (1.0f + __expf(-v)); }

// stage 4096 floats (64x64) into dst
__device__ __forceinline__ void stage64(float* dst, const float* src, int tid) {
    float4* q = (float4*)dst;
    const float4* g = (const float4*)src;
    for (int i = tid; i < 1024; i += TPB) q[i] = __ldg(&g[i]);
}

extern "C" __global__ void __launch_bounds__(TPB, 4)
egnn_kernel(const float* __restrict__ h0,   const float* __restrict__ x0,
            const float* __restrict__ Wemb, const float* __restrict__ bemb,
            const float* __restrict__ We1,  const float* __restrict__ be1,
            const float* __restrict__ We2,  const float* __restrict__ be2,
            const float* __restrict__ Wx,   const float* __restrict__ bx,
            const float* __restrict__ Wh1,  const float* __restrict__ bh1,
            const float* __restrict__ Wh2,  const float* __restrict__ bh2,
            const float* __restrict__ w_act,const float* __restrict__ log_std,
            float* __restrict__ out)
{
    extern __shared__ float sm[];
    float* WA  = sm + OFF_WA;
    float* WB  = sm + OFF_WB;
    float* hs  = sm + OFF_H;
    float* P2p = sm + OFF_P2;
    float* t1s = sm + OFF_P2;          // phase-disjoint reuse
    float* agg = sm + OFF_AGG;
    float* xs0 = sm + OFF_XS0;
    float* xs1 = sm + OFF_XS1;
    float* rad = sm + OFF_RAD;
    float* h0s = sm + OFF_H0S;
    float* ms  = sm + OFF_MS;

    const int tid  = threadIdx.x;
    const int w    = tid >> 5;
    const int lane = tid & 31;
    const int env  = blockIdx.x;
    const int base = env * NAG;
    const int iA = 2 * w, iB = 2 * w + 1;

    // ---------- phase 0: stage x, h0, W_embed ; embed ----------
    if (tid < NAG * NAG) xs0[tid] = __ldg(&x0[base * 12 + tid]);   // base*12 == env*144
    for (int t = tid; t < NAG * 32; t += TPB) h0s[t] = __ldg(&h0[base * 32 + t]);
    {
        float4* q = (float4*)WB;
        const float4* g = (const float4*)Wemb;
        for (int i = tid; i < 512; i += TPB) q[i] = __ldg(&g[i]);
    }
    __syncthreads();
    {   // h = h0 @ Wemb + bemb (2 nodes per warp)
        float a0A = __ldg(&bemb[lane]),      a1A = __ldg(&bemb[lane + 32]);
        float a0B = a0A, a1B = a1A;
        #pragma unroll
        for (int k = 0; k < 32; k++) {
            float w0 = WB[k*64 + lane], w1 = WB[k*64 + lane + 32];
            float hA = h0s[iA*32 + k],  hB = h0s[iB*32 + k];
            a0A += hA*w0; a1A += hA*w1;
            a0B += hB*w0; a1B += hB*w1;
        }
        hs[iA*64 + lane] = a0A; hs[iA*64 + lane + 32] = a1A;
        hs[iB*64 + lane] = a0B; hs[iB*64 + lane + 32] = a1B;
    }

    // ---------- layers ----------
    for (int l = 0; l < 2; l++) {
        __syncthreads();
        float* xsr = (l == 0) ? xs0 : xs1;
        float* xsw = (l == 0) ? xs1 : xs0;
        // stage We1 rows 0..63 -> WA, We2 -> WB ; radial
        stage64(WA, We1 + l * 8448, tid);
        stage64(WB, We2 + l * 4096, tid);
        if (tid < 132) {
            int e = tid, i = e / 11, tt = e - 11 * i, j = tt + (tt >= i);
            float s0 = 0.f, s1 = 0.f, s2 = 0.f, s3 = 0.f;
            #pragma unroll
            for (int d = 0; d < 3; d++) {
                float d0 = xsr[i*12 + d*4 + 0] - xsr[j*12 + d*4 + 0]; s0 += d0*d0;
                float d1 = xsr[i*12 + d*4 + 1] - xsr[j*12 + d*4 + 1]; s1 += d1*d1;
                float d2 = xsr[i*12 + d*4 + 2] - xsr[j*12 + d*4 + 2]; s2 += d2*d2;
                float d3 = xsr[i*12 + d*4 + 3] - xsr[j*12 + d*4 + 3]; s3 += d3*d3;
            }
            ((float4*)rad)[e] = make_float4(s0, s1, s2, s3);
        }
        __syncthreads();

        // ---- P1 pass: hi @ We1[0:64] + be1 (kept in regs) ----
        float PiA0, PiA1, PiB0, PiB1;
        {
            float b0 = __ldg(&be1[l*64 + lane]), b1 = __ldg(&be1[l*64 + lane + 32]);
            float a0A = b0, a1A = b1, a0B = b0, a1B = b1;
            #pragma unroll
            for (int k = 0; k < 64; k++) {
                float w0 = WA[k*64 + lane], w1 = WA[k*64 + lane + 32];
                float hA = hs[iA*64 + k],   hB = hs[iB*64 + k];
                a0A += hA*w0; a1A += hA*w1;
                a0B += hB*w0; a1B += hB*w1;
            }
            PiA0 = a0A; PiA1 = a1A; PiB0 = a0B; PiB1 = a1B;
        }
        __syncthreads();
        // ---- P2 pass: hj @ We1[64:128] -> smem ----
        stage64(WA, We1 + l * 8448 + 4096, tid);
        __syncthreads();
        {
            float a2A = 0.f, a3A = 0.f, a2B = 0.f, a3B = 0.f;
            #pragma unroll
            for (int k = 0; k < 64; k++) {
                float w2 = WA[k*64 + lane], w3 = WA[k*64 + lane + 32];
                float hA = hs[iA*64 + k],   hB = hs[iB*64 + k];
                a2A += hA*w2; a3A += hA*w3;
                a2B += hB*w2; a3B += hB*w3;
            }
            ((float2*)P2p)[iA*32 + lane] = make_float2(a2A, a3A);
            ((float2*)P2p)[iB*32 + lane] = make_float2(a2B, a3B);
        }
        __syncthreads();

        // ---- edge phase: warp owns nodes iA, iB (22 edges, batch 4) ----
        {
            const float4 wxA = __ldg((const float4*)&Wx[l*256 + lane*4]);
            const float4 wxB = __ldg((const float4*)&Wx[l*256 + (lane+32)*4]);
            const float4 bxv = __ldg((const float4*)&bx[l*4]);
            const float be2a = __ldg(&be2[l*64 + lane]);
            const float be2b = __ldg(&be2[l*64 + lane + 32]);
            float wrA[4], wrB[4];
            #pragma unroll
            for (int v = 0; v < 4; v++) {
                wrA[v] = __ldg(&We1[l*8448 + (128+v)*64 + lane]);
                wrB[v] = __ldg(&We1[l*8448 + (128+v)*64 + lane + 32]);
            }
            const float xiA = (lane < 12) ? xsr[iA*12 + lane] : 0.f;
            const float xiB = (lane < 12) ? xsr[iB*12 + lane] : 0.f;
            float agA0 = 0.f, agB0 = 0.f, agA1 = 0.f, agB1 = 0.f;
            float dx0 = 0.f, dx1 = 0.f;
            float* msw = ms + w * 256;

            #pragma unroll
            for (int g0 = 0; g0 < 22; g0 += 4) {
                const int cnt = (22 - g0 < 4) ? (22 - g0) : 4;
                // MLP1
                #pragma unroll
                for (int gg = 0; gg < 4; gg++) if (gg < cnt) {
                    const int t = g0 + gg;
                    const int i  = (t < 11) ? iA : iB;
                    const int tt = (t < 11) ? t : (t - 11);
                    const int j  = tt + (tt >= i);
                    float2 pj = ((const float2*)P2p)[j*32 + lane];
                    float4 rv = ((const float4*)rad)[i*11 + tt];
                    float P1a = (t < 11) ? PiA0 : PiB0;
                    float P1b = (t < 11) ? PiA1 : PiB1;
                    float aA = P1a + pj.x
                             + rv.x*wrA[0] + rv.y*wrA[1] + rv.z*wrA[2] + rv.w*wrA[3];
                    float aB = P1b + pj.y
                             + rv.x*wrB[0] + rv.y*wrB[1] + rv.z*wrB[2] + rv.w*wrB[3];
                    msw[gg*64 + lane]      = siluf(aA);
                    msw[gg*64 + lane + 32] = siluf(aB);
                }
                __syncwarp();
                // MLP2
                float acc0[4] = {be2a, be2a, be2a, be2a};
                float acc1[4] = {be2b, be2b, be2b, be2b};
                #pragma unroll
                for (int k4 = 0; k4 < 16; k4++) {
                    float w00 = WB[(4*k4+0)*64 + lane];
                    float w01 = WB[(4*k4+1)*64 + lane];
                    float w02 = WB[(4*k4+2)*64 + lane];
                    float w03 = WB[(4*k4+3)*64 + lane];
                    float w10 = WB[(4*k4+0)*64 + lane + 32];
                    float w11 = WB[(4*k4+1)*64 + lane + 32];
                    float w12 = WB[(4*k4+2)*64 + lane + 32];
                    float w13 = WB[(4*k4+3)*64 + lane + 32];
                    #pragma unroll
                    for (int gg = 0; gg < 4; gg++) if (gg < cnt) {
                        float4 aq = *(const float4*)&msw[gg*64 + k4*4];
                        acc0[gg] += aq.x*w00 + aq.y*w01 + aq.z*w02 + aq.w*w03;
                        acc1[gg] += aq.x*w10 + aq.y*w11 + aq.z*w12 + aq.w*w13;
                    }
                }
                // epilogue
                #pragma unroll
                for (int gg = 0; gg < 4; gg++) if (gg < cnt) {
                    const int t = g0 + gg;
                    const int tt = (t < 11) ? t : (t - 11);
                    const int i  = (t < 11) ? iA : iB;
                    const int j  = tt + (tt >= i);
                    float m0  = siluf(acc0[gg]);
                    float m1v = siluf(acc1[gg]);
                    if (t < 11) { agA0 += m0; agB0 += m1v; }
                    else        { agA1 += m0; agB1 += m1v; }
                    float p0 = m0*wxA.x + m1v*wxB.x;
                    float p1 = m0*wxA.y + m1v*wxB.y;
                    float p2 = m0*wxA.z + m1v*wxB.z;
                    float p3 = m0*wxA.w + m1v*wxB.w;
                    #pragma unroll
                    for (int off = 16; off; off >>= 1) {
                        p0 += __shfl_xor_sync(0xffffffffu, p0, off);
                        p1 += __shfl_xor_sync(0xffffffffu, p1, off);
                        p2 += __shfl_xor_sync(0xffffffffu, p2, off);
                        p3 += __shfl_xor_sync(0xffffffffu, p3, off);
                    }
                    if (lane < 12) {
                        int v = lane & 3;
                        float wc = (v == 0) ? (p0 + bxv.x) :
                                   (v == 1) ? (p1 + bxv.y) :
                                   (v == 2) ? (p2 + bxv.z) : (p3 + bxv.w);
                        float xi = (t < 11) ? xiA : xiB;
                        float d  = (xi - xsr[j*12 + lane]) * wc;
                        if (t < 11) dx0 += d; else dx1 += d;
                    }
                }
                __syncwarp();
            }
            agg[iA*64 + lane]      = agA0;
            agg[iA*64 + lane + 32] = agB0;
            agg[iB*64 + lane]      = agA1;
            agg[iB*64 + lane + 32] = agB1;
            if (lane < 12) {
                xsw[iA*12 + lane] = xiA + dx0 * (1.0f / 11.0f);
                xsw[iB*12 + lane] = xiB + dx1 * (1.0f / 11.0f);
            }
        }
        __syncthreads();
        // stage Wh1 rows 0..63 -> WA, Wh2 -> WB
        stage64(WA, Wh1 + l * 8192, tid);
        stage64(WB, Wh2 + l * 4096, tid);
        __syncthreads();

        // t1 pass1: h @ Wh1[0:64]
        float a0A, a1A, a0B, a1B;
        {
            float b0 = __ldg(&bh1[l*64 + lane]), b1 = __ldg(&bh1[l*64 + lane + 32]);
            a0A = b0; a1A = b1; a0B = b0; a1B = b1;
            #pragma unroll
            for (int k = 0; k < 64; k++) {
                float w0 = WA[k*64 + lane], w1 = WA[k*64 + lane + 32];
                float hA = hs[iA*64 + k],   hB = hs[iB*64 + k];
                a0A += hA*w0; a1A += hA*w1;
                a0B += hB*w0; a1B += hB*w1;
            }
        }
        __syncthreads();
        stage64(WA, Wh1 + l * 8192 + 4096, tid);
        __syncthreads();
        // t1 pass2: agg @ Wh1[64:128], silu -> t1s
        {
            #pragma unroll
            for (int k = 0; k < 64; k++) {
                float w0 = WA[k*64 + lane], w1 = WA[k*64 + lane + 32];
                float gA = agg[iA*64 + k],  gB = agg[iB*64 + k];
                a0A += gA*w0; a1A += gA*w1;
                a0B += gB*w0; a1B += gB*w1;
            }
            t1s[iA*64 + lane]      = siluf(a0A);
            t1s[iA*64 + lane + 32] = siluf(a1A);
            t1s[iB*64 + lane]      = siluf(a0B);
            t1s[iB*64 + lane + 32] = siluf(a1B);
        }
        __syncthreads();
        // h += t1 @ Wh2 + bh2
        {
            float b0 = __ldg(&bh2[l*64 + lane]), b1 = __ldg(&bh2[l*64 + lane + 32]);
            float c0A = b0, c1A = b1, c0B = b0, c1B = b1;
            #pragma unroll
            for (int k = 0; k < 64; k++) {
                float w0 = WB[k*64 + lane], w1 = WB[k*64 + lane + 32];
                float tA = t1s[iA*64 + k],  tB = t1s[iB*64 + k];
                c0A += tA*w0; c1A += tA*w1;
                c0B += tB*w0; c1B += tB*w1;
            }
            hs[iA*64 + lane]      += c0A;
            hs[iA*64 + lane + 32] += c1A;
            hs[iB*64 + lane]      += c0B;
            hs[iB*64 + lane + 32] += c1B;
        }
    }
    __syncthreads();
    // ---------- output: mu = x . w_act (final x in xs0) ----------
    if (tid < NAG * 3) {
        int a = tid / 3, d = tid - 3 * a;
        float mu = 0.f;
        #pragma unroll
        for (int v = 0; v < 4; v++) mu += xs0[a*12 + d*4 + v] * __ldg(&w_act[v]);
        out[(base + a) * 3 + d] = mu;
        out[NNODE * 3 + (base + a) * 3 + d] =
            -__ldg(&log_std[d]) - 0.91893853320467274178f;
    }
}

extern "C" void kernel_launch(void* const* d_in, const int* in_sizes, int n_in,
                              void* d_out, int out_size)
{
    (void)in_sizes; (void)n_in; (void)out_size;
    cudaFuncSetAttribute(egnn_kernel,
                         cudaFuncAttributeMaxDynamicSharedMemorySize, SMEM_BYTES);
    egnn_kernel<<<NENV, TPB, SMEM_BYTES>>>(
        (const float*)d_in[0],  (const float*)d_in[1],
        (const float*)d_in[2],  (const float*)d_in[3],
        (const float*)d_in[4],  (const float*)d_in[5],
        (const float*)d_in[6],  (const float*)d_in[7],
        (const float*)d_in[8],  (const float*)d_in[9],
        (const float*)d_in[10], (const float*)d_in[11],
        (const float*)d_in[12], (const float*)d_in[13],
        (const float*)d_in[14], (const float*)d_in[15],
        (float*)d_out);
}

// round 7
// speedup vs baseline: 1.4188x; 1.0228x over previous
#include <cuda_runtime.h>

#define NAG    12
#define NENV   4096
#define NNODE  (NENV*NAG)
#define TPB    192
#define NW     6

// shared float offsets (identical to R3)
#define OFF_WA   0        // 8192 (We1[0:128] / Wh1)
#define OFF_WB   8192     // 4096 (Wemb / We2 / Wh2)
#define OFF_H    12288    // 12x64
#define OFF_P2   13056    // P2 float2[12][32] ; reused as t1 [12][64]
#define OFF_AGG  13824    // 12x64
#define OFF_XS0  14592    // 144
#define OFF_XS1  14736    // 144
#define OFF_RAD  14880    // 132x4
#define OFF_H0S  15408    // 12x32
#define OFF_MS   15792    // 6 warps x 512
#define SMEM_FLOATS 18864
#define SMEM_BYTES  (SMEM_FLOATS*4)

#define COMP(v,q) ((q)==0?(v).x:(q)==1?(v).y:(q)==2?(v).z:(v).w)

__device__ __forceinline__ float siluf(float v) { return v / (1.0f + __expf(-v)); }

extern "C" __global__ void __launch_bounds__(TPB, 3)
egnn_kernel(const float* __restrict__ h0,   const float* __restrict__ x0,
            const float* __restrict__ Wemb, const float* __restrict__ bemb,
            const float* __restrict__ We1,  const float* __restrict__ be1,
            const float* __restrict__ We2,  const float* __restrict__ be2,
            const float* __restrict__ Wx,   const float* __restrict__ bx,
            const float* __restrict__ Wh1,  const float* __restrict__ bh1,
            const float* __restrict__ Wh2,  const float* __restrict__ bh2,
            const float* __restrict__ w_act,const float* __restrict__ log_std,
            float* __restrict__ out)
{
    extern __shared__ float sm[];
    float* WA  = sm + OFF_WA;
    float* WB  = sm + OFF_WB;
    float* hs  = sm + OFF_H;
    float* P2p = sm + OFF_P2;
    float* t1s = sm + OFF_P2;          // phase-disjoint reuse
    float* agg = sm + OFF_AGG;
    float* xs0 = sm + OFF_XS0;
    float* xs1 = sm + OFF_XS1;
    float* rad = sm + OFF_RAD;
    float* h0s = sm + OFF_H0S;
    float* ms  = sm + OFF_MS;

    const int tid  = threadIdx.x;
    const int w    = tid >> 5;
    const int lane = tid & 31;
    const int env  = blockIdx.x;
    const int base = env * NAG;
    const int iA = 2 * w, iB = 2 * w + 1;

    // ---------- phase 0: stage x, h0, W_embed ; embed ----------
    if (tid < NAG * NAG) xs0[tid] = __ldg(&x0[base * 12 + tid]);
    for (int t = tid; t < NAG * 32; t += TPB) h0s[t] = __ldg(&h0[base * 32 + t]);
    {
        float4* q = (float4*)WB;
        const float4* g = (const float4*)Wemb;
        for (int i = tid; i < 512; i += TPB) q[i] = __ldg(&g[i]);
    }
    __syncthreads();
    {   // h = h0 @ Wemb + bemb (2 nodes per warp)
        float a0A = __ldg(&bemb[lane]),      a1A = __ldg(&bemb[lane + 32]);
        float a0B = a0A, a1B = a1A;
        #pragma unroll
        for (int k4 = 0; k4 < 8; k4++) {
            float4 hA4 = *(const float4*)&h0s[iA*32 + k4*4];
            float4 hB4 = *(const float4*)&h0s[iB*32 + k4*4];
            #pragma unroll
            for (int q = 0; q < 4; q++) {
                int k = k4*4 + q;
                float w0 = WB[k*64 + lane], w1 = WB[k*64 + lane + 32];
                float hA = COMP(hA4,q), hB = COMP(hB4,q);
                a0A += hA*w0; a1A += hA*w1;
                a0B += hB*w0; a1B += hB*w1;
            }
        }
        hs[iA*64 + lane] = a0A; hs[iA*64 + lane + 32] = a1A;
        hs[iB*64 + lane] = a0B; hs[iB*64 + lane + 32] = a1B;
    }

    // ---------- layers ----------
    for (int l = 0; l < 2; l++) {
        __syncthreads();
        float* xsr = (l == 0) ? xs0 : xs1;
        float* xsw = (l == 0) ? xs1 : xs0;
        {   // stage We1 rows 0..127 -> WA, We2 -> WB
            float4* q = (float4*)WA;
            const float4* g = (const float4*)(We1 + l * 8448);
            for (int i = tid; i < 2048; i += TPB) q[i] = __ldg(&g[i]);
            float4* q2 = (float4*)WB;
            const float4* g2 = (const float4*)(We2 + l * 4096);
            for (int i = tid; i < 1024; i += TPB) q2[i] = __ldg(&g2[i]);
        }
        if (tid < 132) {   // radial per edge
            int e = tid, i = e / 11, tt = e - 11 * i, j = tt + (tt >= i);
            float s0 = 0.f, s1 = 0.f, s2 = 0.f, s3 = 0.f;
            #pragma unroll
            for (int d = 0; d < 3; d++) {
                float d0 = xsr[i*12 + d*4 + 0] - xsr[j*12 + d*4 + 0]; s0 += d0*d0;
                float d1 = xsr[i*12 + d*4 + 1] - xsr[j*12 + d*4 + 1]; s1 += d1*d1;
                float d2 = xsr[i*12 + d*4 + 2] - xsr[j*12 + d*4 + 2]; s2 += d2*d2;
                float d3 = xsr[i*12 + d*4 + 3] - xsr[j*12 + d*4 + 3]; s3 += d3*d3;
            }
            ((float4*)rad)[e] = make_float4(s0, s1, s2, s3);
        }
        __syncthreads();

        // ---- P-phase (2 nodes per warp): P1 in regs, P2 -> smem ----
        float PiA0, PiA1, PiB0, PiB1;
        {
            float b0 = __ldg(&be1[l*64 + lane]), b1 = __ldg(&be1[l*64 + lane + 32]);
            float a0A = b0, a1A = b1, a2A = 0.f, a3A = 0.f;
            float a0B = b0, a1B = b1, a2B = 0.f, a3B = 0.f;
            #pragma unroll
            for (int k4 = 0; k4 < 16; k4++) {
                float4 hA4 = *(const float4*)&hs[iA*64 + k4*4];
                float4 hB4 = *(const float4*)&hs[iB*64 + k4*4];
                #pragma unroll
                for (int q = 0; q < 4; q++) {
                    int k = k4*4 + q;
                    float w0 = WA[k*64 + lane],      w1 = WA[k*64 + lane + 32];
                    float w2 = WA[(64+k)*64 + lane], w3 = WA[(64+k)*64 + lane + 32];
                    float hA = COMP(hA4,q), hB = COMP(hB4,q);
                    a0A += hA*w0; a1A += hA*w1; a2A += hA*w2; a3A += hA*w3;
                    a0B += hB*w0; a1B += hB*w1; a2B += hB*w2; a3B += hB*w3;
                }
            }
            PiA0 = a0A; PiA1 = a1A; PiB0 = a0B; PiB1 = a1B;
            ((float2*)P2p)[iA*32 + lane] = make_float2(a2A, a3A);
            ((float2*)P2p)[iB*32 + lane] = make_float2(a2B, a3B);
        }
        __syncthreads();

        // ---- edge phase: warp owns nodes iA, iB (22 edges, batch 8) ----
        {
            const float4 wxA = __ldg((const float4*)&Wx[l*256 + lane*4]);
            const float4 wxB = __ldg((const float4*)&Wx[l*256 + (lane+32)*4]);
            const float4 bxv = __ldg((const float4*)&bx[l*4]);
            const float be2a = __ldg(&be2[l*64 + lane]);
            const float be2b = __ldg(&be2[l*64 + lane + 32]);
            float wrA[4], wrB[4];
            #pragma unroll
            for (int v = 0; v < 4; v++) {
                wrA[v] = __ldg(&We1[l*8448 + (128+v)*64 + lane]);
                wrB[v] = __ldg(&We1[l*8448 + (128+v)*64 + lane + 32]);
            }
            const float xiA = (lane < 12) ? xsr[iA*12 + lane] : 0.f;
            const float xiB = (lane < 12) ? xsr[iB*12 + lane] : 0.f;
            float agA0 = 0.f, agB0 = 0.f, agA1 = 0.f, agB1 = 0.f;
            float dx0 = 0.f, dx1 = 0.f;
            float* msw = ms + w * 512;
            const bool lb0 = lane & 1, lb1 = lane & 2;

            #pragma unroll
            for (int g0 = 0; g0 < 22; g0 += 8) {
                const int cnt = (22 - g0 < 8) ? (22 - g0) : 8;
                // MLP1
                #pragma unroll
                for (int gg = 0; gg < 8; gg++) if (gg < cnt) {
                    const int t = g0 + gg;
                    const int i  = (t < 11) ? iA : iB;
                    const int tt = (t < 11) ? t : (t - 11);
                    const int j  = tt + (tt >= i);
                    float2 pj = ((const float2*)P2p)[j*32 + lane];
                    float4 rv = ((const float4*)rad)[i*11 + tt];
                    float P1a = (t < 11) ? PiA0 : PiB0;
                    float P1b = (t < 11) ? PiA1 : PiB1;
                    float aA = P1a + pj.x
                             + rv.x*wrA[0] + rv.y*wrA[1] + rv.z*wrA[2] + rv.w*wrA[3];
                    float aB = P1b + pj.y
                             + rv.x*wrB[0] + rv.y*wrB[1] + rv.z*wrB[2] + rv.w*wrB[3];
                    msw[gg*64 + lane]      = siluf(aA);
                    msw[gg*64 + lane + 32] = siluf(aB);
                }
                __syncwarp();
                // MLP2: weights read once per k4 for up to 8 edges
                float acc0[8], acc1[8];
                #pragma unroll
                for (int gg = 0; gg < 8; gg++) { acc0[gg] = be2a; acc1[gg] = be2b; }
                #pragma unroll
                for (int k4 = 0; k4 < 16; k4++) {
                    float w00 = WB[(4*k4+0)*64 + lane];
                    float w01 = WB[(4*k4+1)*64 + lane];
                    float w02 = WB[(4*k4+2)*64 + lane];
                    float w03 = WB[(4*k4+3)*64 + lane];
                    float w10 = WB[(4*k4+0)*64 + lane + 32];
                    float w11 = WB[(4*k4+1)*64 + lane + 32];
                    float w12 = WB[(4*k4+2)*64 + lane + 32];
                    float w13 = WB[(4*k4+3)*64 + lane + 32];
                    #pragma unroll
                    for (int gg = 0; gg < 8; gg++) if (gg < cnt) {
                        float4 aq = *(const float4*)&msw[gg*64 + k4*4];
                        acc0[gg] += aq.x*w00 + aq.y*w01 + aq.z*w02 + aq.w*w03;
                        acc1[gg] += aq.x*w10 + aq.y*w11 + aq.z*w12 + aq.w*w13;
                    }
                }
                // epilogue: 6-shuffle multi-value reduce
                #pragma unroll
                for (int gg = 0; gg < 8; gg++) if (gg < cnt) {
                    const int t = g0 + gg;
                    const int tt = (t < 11) ? t : (t - 11);
                    const int i  = (t < 11) ? iA : iB;
                    const int j  = tt + (tt >= i);
                    float m0  = siluf(acc0[gg]);
                    float m1v = siluf(acc1[gg]);
                    if (t < 11) { agA0 += m0; agB0 += m1v; }
                    else        { agA1 += m0; agB1 += m1v; }
                    float p0 = m0*wxA.x + m1v*wxB.x;
                    float p1 = m0*wxA.y + m1v*wxB.y;
                    float p2 = m0*wxA.z + m1v*wxB.z;
                    float p3 = m0*wxA.w + m1v*wxB.w;
                    // round 1 (xor 1): pair-sum per value, 2 shuffles
                    float sA = __shfl_xor_sync(0xffffffffu, lb0 ? p0 : p1, 1);
                    float A  = (lb0 ? p1 : p0) + sA;
                    float sC = __shfl_xor_sync(0xffffffffu, lb0 ? p2 : p3, 1);
                    float C  = (lb0 ? p3 : p2) + sC;
                    // round 2 (xor 2): 1 shuffle -> lane holds value lane&3 over 4-lane group
                    float sR = __shfl_xor_sync(0xffffffffu, lb1 ? A : C, 2);
                    float R  = (lb1 ? C : A) + sR;
                    // rounds 3-5: plain butterfly
                    R += __shfl_xor_sync(0xffffffffu, R, 4);
                    R += __shfl_xor_sync(0xffffffffu, R, 8);
                    R += __shfl_xor_sync(0xffffffffu, R, 16);
                    if (lane < 12) {
                        int v = lane & 3;
                        float wc = R + ((v == 0) ? bxv.x : (v == 1) ? bxv.y :
                                        (v == 2) ? bxv.z : bxv.w);
                        float xi = (t < 11) ? xiA : xiB;
                        float d  = (xi - xsr[j*12 + lane]) * wc;
                        if (t < 11) dx0 += d; else dx1 += d;
                    }
                }
                __syncwarp();
            }
            agg[iA*64 + lane]      = agA0;
            agg[iA*64 + lane + 32] = agB0;
            agg[iB*64 + lane]      = agA1;
            agg[iB*64 + lane + 32] = agB1;
            if (lane < 12) {
                xsw[iA*12 + lane] = xiA + dx0 * (1.0f / 11.0f);
                xsw[iB*12 + lane] = xiB + dx1 * (1.0f / 11.0f);
            }
        }
        __syncthreads();
        {   // stage Wh1 -> WA, Wh2 -> WB
            float4* q = (float4*)WA;
            const float4* g = (const float4*)(Wh1 + l * 8192);
            for (int i = tid; i < 2048; i += TPB) q[i] = __ldg(&g[i]);
            float4* q2 = (float4*)WB;
            const float4* g2 = (const float4*)(Wh2 + l * 4096);
            for (int i = tid; i < 1024; i += TPB) q2[i] = __ldg(&g2[i]);
        }
        __syncthreads();

        // t1 = silu([h, agg] @ Wh1 + bh1)
        {
            float b0 = __ldg(&bh1[l*64 + lane]), b1 = __ldg(&bh1[l*64 + lane + 32]);
            float a0A = b0, a1A = b1, a0B = b0, a1B = b1;
            #pragma unroll
            for (int k4 = 0; k4 < 16; k4++) {
                float4 hA4 = *(const float4*)&hs[iA*64 + k4*4];
                float4 hB4 = *(const float4*)&hs[iB*64 + k4*4];
                #pragma unroll
                for (int q = 0; q < 4; q++) {
                    int k = k4*4 + q;
                    float w0 = WA[k*64 + lane], w1 = WA[k*64 + lane + 32];
                    float hA = COMP(hA4,q), hB = COMP(hB4,q);
                    a0A += hA*w0; a1A += hA*w1;
                    a0B += hB*w0; a1B += hB*w1;
                }
            }
            #pragma unroll
            for (int k4 = 0; k4 < 16; k4++) {
                float4 gA4 = *(const float4*)&agg[iA*64 + k4*4];
                float4 gB4 = *(const float4*)&agg[iB*64 + k4*4];
                #pragma unroll
                for (int q = 0; q < 4; q++) {
                    int k = k4*4 + q;
                    float w0 = WA[(64+k)*64 + lane], w1 = WA[(64+k)*64 + lane + 32];
                    float gA = COMP(gA4,q), gB = COMP(gB4,q);
                    a0A += gA*w0; a1A += gA*w1;
                    a0B += gB*w0; a1B += gB*w1;
                }
            }
            float s0A = siluf(a0A), s1A = siluf(a1A);
            float s0B = siluf(a0B), s1B = siluf(a1B);
            __syncthreads();   // P2p (aliased by t1s) fully consumed before overwrite
            t1s[iA*64 + lane] = s0A; t1s[iA*64 + lane + 32] = s1A;
            t1s[iB*64 + lane] = s0B; t1s[iB*64 + lane + 32] = s1B;
        }
        __syncthreads();
        // h += t1 @ Wh2 + bh2
        {
            float b0 = __ldg(&bh2[l*64 + lane]), b1 = __ldg(&bh2[l*64 + lane + 32]);
            float a0A = b0, a1A = b1, a0B = b0, a1B = b1;
            #pragma unroll
            for (int k4 = 0; k4 < 16; k4++) {
                float4 tA4 = *(const float4*)&t1s[iA*64 + k4*4];
                float4 tB4 = *(const float4*)&t1s[iB*64 + k4*4];
                #pragma unroll
                for (int q = 0; q < 4; q++) {
                    int k = k4*4 + q;
                    float w0 = WB[k*64 + lane], w1 = WB[k*64 + lane + 32];
                    float tA = COMP(tA4,q), tB = COMP(tB4,q);
                    a0A += tA*w0; a1A += tA*w1;
                    a0B += tB*w0; a1B += tB*w1;
                }
            }
            hs[iA*64 + lane]      += a0A;
            hs[iA*64 + lane + 32] += a1A;
            hs[iB*64 + lane]      += a0B;
            hs[iB*64 + lane + 32] += a1B;
        }
    }
    __syncthreads();
    // ---------- output: mu = x . w_act (final x in xs0) ----------
    if (tid < NAG * 3) {
        int a = tid / 3, d = tid - 3 * a;
        float mu = 0.f;
        #pragma unroll
        for (int v = 0; v < 4; v++) mu += xs0[a*12 + d*4 + v] * __ldg(&w_act[v]);
        out[(base + a) * 3 + d] = mu;
        out[NNODE * 3 + (base + a) * 3 + d] =
            -__ldg(&log_std[d]) - 0.91893853320467274178f;
    }
}

extern "C" void kernel_launch(void* const* d_in, const int* in_sizes, int n_in,
                              void* d_out, int out_size)
{
    (void)in_sizes; (void)n_in; (void)out_size;
    cudaFuncSetAttribute(egnn_kernel,
                         cudaFuncAttributeMaxDynamicSharedMemorySize, SMEM_BYTES);
    egnn_kernel<<<NENV, TPB, SMEM_BYTES>>>(
        (const float*)d_in[0],  (const float*)d_in[1],
        (const float*)d_in[2],  (const float*)d_in[3],
        (const float*)d_in[4],  (const float*)d_in[5],
        (const float*)d_in[6],  (const float*)d_in[7],
        (const float*)d_in[8],  (const float*)d_in[9],
        (const float*)d_in[10], (const float*)d_in[11],
        (const float*)d_in[12], (const float*)d_in[13],
        (const float*)d_in[14], (const float*)d_in[15],
        (float*)d_out);
}